// round 1
// baseline (speedup 1.0000x reference)
#include <cuda_runtime.h>
#include <cuda_bf16.h>

#define BB  8192
#define BLK 256
#define JC  512   // j-chunk cached in smem per block

__device__ double             g_sum;
__device__ unsigned long long g_cnt;
__device__ int                g_nev;
__device__ float2             g_ev[BB];   // {time_i, 1.0f + risk_i} for event rows

__global__ void k_init() {
    g_sum = 0.0;
    g_cnt = 0ull;
    g_nev = 0;
}

__global__ void k_compact(const float* __restrict__ risk,
                          const float* __restrict__ tm,
                          const int*   __restrict__ ev) {
    int i = blockIdx.x * blockDim.x + threadIdx.x;
    if (i < BB && ev[i] == 1) {
        int p = atomicAdd(&g_nev, 1);
        g_ev[p] = make_float2(tm[i], 1.0f + risk[i]);
    }
}

__global__ void __launch_bounds__(BLK) k_main(const float* __restrict__ risk,
                                              const float* __restrict__ tm) {
    __shared__ float2 sj[JC];
    int j0 = blockIdx.y * JC;
    #pragma unroll
    for (int j = threadIdx.x; j < JC; j += BLK) {
        sj[j] = make_float2(tm[j0 + j], risk[j0 + j]);
    }
    __syncthreads();

    int   ii   = blockIdx.x * BLK + threadIdx.x;
    float lsum = 0.f;
    int   lcnt = 0;
    int   nev  = g_nev;

    if (ii < nev) {
        float2 e  = g_ev[ii];
        float  ti = e.x;
        float  ci = e.y;   // 1 + risk_i
        #pragma unroll 8
        for (int j = 0; j < JC; j++) {
            float2 p = sj[j];           // {time_j, risk_j} — smem broadcast
            float  h = fmaxf(ci - p.y, 0.f);
            if (ti < p.x) {             // pair is valid
                lcnt += 1;
                lsum += h;
            }
        }
    }

    // warp reduce
    #pragma unroll
    for (int o = 16; o; o >>= 1) {
        lsum += __shfl_down_sync(0xffffffffu, lsum, o);
        lcnt += __shfl_down_sync(0xffffffffu, lcnt, o);
    }

    __shared__ float ws[BLK / 32];
    __shared__ int   wc[BLK / 32];
    int lane = threadIdx.x & 31;
    int w    = threadIdx.x >> 5;
    if (lane == 0) { ws[w] = lsum; wc[w] = lcnt; }
    __syncthreads();

    if (threadIdx.x == 0) {
        float s = 0.f;
        int   c = 0;
        #pragma unroll
        for (int k = 0; k < BLK / 32; k++) { s += ws[k]; c += wc[k]; }
        if (c != 0 || s != 0.f) {
            atomicAdd(&g_sum, (double)s);
            atomicAdd(&g_cnt, (unsigned long long)c);
        }
    }
}

__global__ void k_fin(float* out) {
    unsigned long long c = g_cnt;
    out[0] = (c == 0ull) ? 0.f : (float)(g_sum / (double)c);
}

extern "C" void kernel_launch(void* const* d_in, const int* in_sizes, int n_in,
                              void* d_out, int out_size) {
    // metadata order: z (unused), risk, time, event
    const float* risk = (const float*)d_in[1];
    const float* tm   = (const float*)d_in[2];
    const int*   ev   = (const int*)d_in[3];
    float*       out  = (float*)d_out;

    k_init<<<1, 1>>>();
    k_compact<<<BB / BLK, BLK>>>(risk, tm, ev);
    dim3 grid(BB / BLK, BB / JC);
    k_main<<<grid, BLK>>>(risk, tm);
    k_fin<<<1, 1>>>(out);
}

// round 2
// speedup vs baseline: 1.1950x; 1.1950x over previous
#include <cuda_runtime.h>
#include <cuda_bf16.h>

#define BB    8192
#define BLK   256
#define GRID  296          // 2 blocks/SM on 148 SMs -> guaranteed co-resident
#define IR    4            // i-values per thread (register blocking)
#define JC    64           // j-chunk cached in smem per tile
#define NJB   (BB / JC)    // 128 j-chunks
#define IBLK  (BLK * IR)   // 1024 compacted i per i-tile

__device__ float2   g_ev[BB];    // {time_i, 1+risk_i} compacted event rows
__device__ float2   g_j[BB];     // {time_j, risk_j} packed
__device__ int      g_nev;
__device__ unsigned g_bar;
__device__ unsigned g_done;
__device__ float    g_ps[GRID];
__device__ float    g_pc[GRID];

__global__ void __launch_bounds__(BLK) k_all(const float* __restrict__ risk,
                                             const float* __restrict__ tm,
                                             const int*   __restrict__ ev,
                                             float*       __restrict__ out) {
    const int tid  = threadIdx.x;
    const int gtid = blockIdx.x * BLK + tid;

    // ---- Phase A: pack j-array + warp-aggregated event compaction ----
    if (gtid < BB) {                       // whole warps in/out (8192 % 256 == 0)
        float t = tm[gtid];
        float r = risk[gtid];
        g_j[gtid] = make_float2(t, r);
        int e = ev[gtid];
        unsigned m = __ballot_sync(0xffffffffu, e == 1);
        int base = 0;
        if ((tid & 31) == 0 && m) base = atomicAdd(&g_nev, __popc(m));
        base = __shfl_sync(0xffffffffu, base, 0);
        if (e == 1) {
            int p = base + __popc(m & ((1u << (tid & 31)) - 1u));
            g_ev[p] = make_float2(t, 1.0f + r);
        }
    }

    // ---- software grid barrier ----
    __syncthreads();
    if (tid == 0) {
        __threadfence();
        atomicAdd(&g_bar, 1);
        while (*(volatile unsigned*)&g_bar < GRID) { }
        __threadfence();
    }
    __syncthreads();

    const int nev = *(volatile int*)&g_nev;

    // ---- Phase B: pair loop over (i-tile, j-tile) work units ----
    __shared__ float2 sj[JC];
    float lsum = 0.f;
    float lcnt = 0.f;

    const int n_ib   = (nev + IBLK - 1) / IBLK;
    const int ntiles = n_ib * NJB;

    for (int tl = blockIdx.x; tl < ntiles; tl += GRID) {
        int ib = tl / NJB;
        int jb = tl - ib * NJB;

        __syncthreads();                       // smem safe to overwrite
        if (tid < JC) sj[tid] = g_j[jb * JC + tid];
        __syncthreads();

        float ti[IR], ci[IR];
        #pragma unroll
        for (int k = 0; k < IR; k++) {
            int i = ib * IBLK + k * BLK + tid;
            if (i < nev) {
                float2 e = g_ev[i];
                ti[k] = e.x; ci[k] = e.y;
            } else {
                ti[k] = __int_as_float(0x7f800000);  // +inf -> never valid
                ci[k] = 0.f;
            }
        }

        #pragma unroll 4
        for (int j = 0; j < JC; j++) {
            float2 p = sj[j];                  // one LDS.64 serves IR=4 pairs
            #pragma unroll
            for (int k = 0; k < IR; k++) {
                float h = fmaxf(ci[k] - p.y, 0.f);
                if (ti[k] < p.x) { lsum += h; lcnt += 1.f; }
            }
        }
    }

    // ---- block reduce -> per-block partial (no global atomics) ----
    #pragma unroll
    for (int o = 16; o; o >>= 1) {
        lsum += __shfl_down_sync(0xffffffffu, lsum, o);
        lcnt += __shfl_down_sync(0xffffffffu, lcnt, o);
    }
    __shared__ float ws[BLK / 32], wc[BLK / 32];
    if ((tid & 31) == 0) { ws[tid >> 5] = lsum; wc[tid >> 5] = lcnt; }
    __syncthreads();
    if (tid == 0) {
        float s = 0.f, c = 0.f;
        #pragma unroll
        for (int k = 0; k < BLK / 32; k++) { s += ws[k]; c += wc[k]; }
        g_ps[blockIdx.x] = s;
        g_pc[blockIdx.x] = c;
    }

    // ---- finish: last block reduces partials (double) and writes output ----
    __shared__ int amLast;
    if (tid == 0) {
        __threadfence();
        amLast = (atomicAdd(&g_done, 1) == GRID - 1);
    }
    __syncthreads();

    if (amLast) {
        __threadfence();
        double s = 0.0, c = 0.0;
        for (int i = tid; i < GRID; i += BLK) {
            s += (double)g_ps[i];
            c += (double)g_pc[i];
        }
        #pragma unroll
        for (int o = 16; o; o >>= 1) {
            s += __shfl_down_sync(0xffffffffu, s, o);
            c += __shfl_down_sync(0xffffffffu, c, o);
        }
        __shared__ double fs[BLK / 32], fc[BLK / 32];
        if ((tid & 31) == 0) { fs[tid >> 5] = s; fc[tid >> 5] = c; }
        __syncthreads();
        if (tid == 0) {
            double S = 0.0, C = 0.0;
            #pragma unroll
            for (int k = 0; k < BLK / 32; k++) { S += fs[k]; C += fc[k]; }
            out[0] = (C == 0.0) ? 0.f : (float)(S / C);
            g_bar  = 0;          // reset for next graph replay
            g_done = 0;
            g_nev  = 0;
        }
    }
}

extern "C" void kernel_launch(void* const* d_in, const int* in_sizes, int n_in,
                              void* d_out, int out_size) {
    // metadata order: z (unused), risk, time, event
    const float* risk = (const float*)d_in[1];
    const float* tm   = (const float*)d_in[2];
    const int*   ev   = (const int*)d_in[3];
    float*       out  = (float*)d_out;

    k_all<<<GRID, BLK>>>(risk, tm, ev, out);
}